// round 5
// baseline (speedup 1.0000x reference)
#include <cuda_runtime.h>
#include <cstdint>

// LIF recurrence: 64-row ILP-2 tiles + per-warp double-buffered cp.async pipeline.
// x: [B*N, T] fp32, T=100 contiguous.
//   u_t = decay*u_{t-1} + x_t - o_{t-1}*VTH ; o_t = (u_t - VTH > 0) ? 1 : 0
//
// Warp tile = 64 consecutive rows = 25600B contiguous span. Each warp:
//   prefetch(tile k+1) -> wait(tile k) -> scan k (2 chains/thread) -> store k
// so a full 25.6KB of reads per warp is outstanding at all times.

#define VTH 0.5f
#define T_STEPS 100
#define T_VEC (T_STEPS / 4)                   // 25
#define ROWS_PER_TILE 64
#define TILE_FLOATS (ROWS_PER_TILE * T_STEPS) // 6400 floats = 25600 B
#define TILE_VEC (TILE_FLOATS / 4)            // 1600 float4
#define VEC_PER_LANE (TILE_VEC / 32)          // 50
#define WARPS_PER_BLOCK 2
#define BLOCK_THREADS (WARPS_PER_BLOCK * 32)
#define SMEM_BYTES (WARPS_PER_BLOCK * 2 * TILE_FLOATS * sizeof(float)) // 102400
#define GRID_BLOCKS 304                       // 2 per SM on 152 SMs

__device__ __forceinline__ void cp_async16(uint32_t smem_dst, const void* gmem_src) {
    asm volatile("cp.async.cg.shared.global [%0], [%1], 16;\n"
                 :: "r"(smem_dst), "l"(gmem_src));
}
__device__ __forceinline__ void cp_async_commit() {
    asm volatile("cp.async.commit_group;\n" ::: "memory");
}
__device__ __forceinline__ void cp_async_wait_1() {
    asm volatile("cp.async.wait_group 1;\n" ::: "memory");
}
__device__ __forceinline__ void cp_async_wait_0() {
    asm volatile("cp.async.wait_group 0;\n" ::: "memory");
}

#define LIF_STEP(u, o, xv)                      \
    do {                                        \
        u = fmaf(decay, u, xv);                 \
        u = fmaf(-VTH, o, u);                   \
        o = (u > VTH) ? 1.0f : 0.0f;            \
    } while (0)

__device__ __forceinline__ void prefetch_tile(const float* __restrict__ x,
                                              int tile, float* buf, int lane)
{
    const float4* g = reinterpret_cast<const float4*>(
        x + (size_t)tile * TILE_FLOATS);
    uint32_t s = (uint32_t)__cvta_generic_to_shared(buf);
#pragma unroll
    for (int i = 0; i < VEC_PER_LANE; ++i) {
        int idx = lane + 32 * i;                 // coalesced, contiguous span
        cp_async16(s + (uint32_t)idx * 16u, g + idx);
    }
    cp_async_commit();
}

__global__ void __launch_bounds__(BLOCK_THREADS) lif_kernel(
    const float* __restrict__ x,
    const float* __restrict__ decay_p,
    float* __restrict__ out,
    int n_neurons)
{
    extern __shared__ float smem[];

    const int warp = threadIdx.x >> 5;
    const int lane = threadIdx.x & 31;

    const int gwarp  = blockIdx.x * WARPS_PER_BLOCK + warp;
    const int nwarps = gridDim.x * WARPS_PER_BLOCK;       // 608
    const int ntiles = n_neurons / ROWS_PER_TILE;         // 4096

    const float decay = __ldg(decay_p);

    float* buf0 = smem + (size_t)warp * 2 * TILE_FLOATS;
    float* buf1 = buf0 + TILE_FLOATS;

    int t = gwarp;
    if (t < ntiles) prefetch_tile(x, t, buf0, lane);

    int k = 0;
    for (; t < ntiles; t += nwarps, k ^= 1) {
        float* cur = k ? buf1 : buf0;
        float* nxt = k ? buf0 : buf1;

        int tn = t + nwarps;
        if (tn < ntiles) {
            prefetch_tile(x, tn, nxt, lane);   // keep reads in flight during scan
            cp_async_wait_1();                 // tile t's group complete
        } else {
            cp_async_wait_0();
        }
        __syncwarp();

        // ---- scan: two interleaved chains per thread (rows lane, lane+32) ----
        {
            float4* r0 = reinterpret_cast<float4*>(cur + (size_t)lane * T_STEPS);
            float4* r1 = reinterpret_cast<float4*>(cur + (size_t)(lane + 32) * T_STEPS);

            float u0 = 0.0f, o0 = 0.0f;
            float u1 = 0.0f, o1 = 0.0f;
#pragma unroll
            for (int q = 0; q < T_VEC; ++q) {
                float4 a = r0[q];
                float4 b = r1[q];
                float4 oa, ob;

                LIF_STEP(u0, o0, a.x);  oa.x = o0;
                LIF_STEP(u1, o1, b.x);  ob.x = o1;
                LIF_STEP(u0, o0, a.y);  oa.y = o0;
                LIF_STEP(u1, o1, b.y);  ob.y = o1;
                LIF_STEP(u0, o0, a.z);  oa.z = o0;
                LIF_STEP(u1, o1, b.z);  ob.z = o1;
                LIF_STEP(u0, o0, a.w);  oa.w = o0;
                LIF_STEP(u1, o1, b.w);  ob.w = o1;

                r0[q] = oa;            // spikes overwrite consumed input
                r1[q] = ob;
            }
        }
        __syncwarp();

        // ---- coalesced store of the spike tile ----
        {
            const float4* c4 = reinterpret_cast<const float4*>(cur);
            float4* go = reinterpret_cast<float4*>(
                out + (size_t)t * TILE_FLOATS);
#pragma unroll
            for (int i = 0; i < VEC_PER_LANE; ++i) {
                int idx = lane + 32 * i;
                go[idx] = c4[idx];
            }
        }
        __syncwarp();   // 'cur' reads done before it is refilled next iteration
    }
}

extern "C" void kernel_launch(void* const* d_in, const int* in_sizes, int n_in,
                              void* d_out, int out_size)
{
    const float* x       = (const float*)d_in[0];
    const float* decay_p = (const float*)d_in[1];
    float*       out     = (float*)d_out;

    int n_neurons = in_sizes[0] / T_STEPS;   // 262144

    cudaFuncSetAttribute(lif_kernel,
                         cudaFuncAttributeMaxDynamicSharedMemorySize,
                         (int)SMEM_BYTES);

    lif_kernel<<<GRID_BLOCKS, BLOCK_THREADS, SMEM_BYTES>>>(x, decay_p, out, n_neurons);
}